// round 8
// baseline (speedup 1.0000x reference)
#include <cuda_runtime.h>

#define B_ 8
#define P_ 10
#define S_ 160
#define FX_ 11
#define D_ 64
#define DFF_ 256
#define NROW (B_*P_*S_)   /* 12800 */
#define NPART (B_*P_)     /* 80 */

/* output layout (tuple order): pred, pred_resampl, K, V, R, attn_weights */
#define OFF_PRED  0
#define OFF_PRED2 (NROW)
#define OFF_K     (2*NROW)
#define OFF_V     (OFF_K + NROW*D_)
#define OFF_R     (OFF_V + NROW*D_)
#define OFF_ATTN  (OFF_R + NROW*D_)

/* scratch (no cudaMalloc allowed) */
__device__ float g_x[NROW*D_];
__device__ float g_q[NROW*D_];
__device__ float g_z[NROW*D_];
__device__ float g_fw[4*704];   /* fused 11x64 weights: x,q,k,v */
__device__ float g_fb[4*64];    /* fused biases */

typedef unsigned long long u64t;

__device__ __forceinline__ void fma2p(u64t& acc, u64t a, u64t b) {
    asm("fma.rn.f32x2 %0, %1, %2, %0;" : "+l"(acc) : "l"(a), "l"(b));
}
__device__ __forceinline__ u64t dup2(float x) {
    u64t r;
    asm("mov.b64 %0, {%1, %1};" : "=l"(r) : "f"(x));
    return r;
}
__device__ __forceinline__ void unpack2(float& lo, float& hi, u64t v) {
    asm("mov.b64 {%0, %1}, %2;" : "=f"(lo), "=f"(hi) : "l"(v));
}

/* ------------------------------------------------------------------ */
/* K0: fold Wp into Wq/Wk/Wv. Attention scale 1/8 folded into Wq.     */
/* ------------------------------------------------------------------ */
__global__ void __launch_bounds__(256) k_fold(
    const float* __restrict__ Wp, const float* __restrict__ bp,
    const float* __restrict__ Wq, const float* __restrict__ bq,
    const float* __restrict__ Wk, const float* __restrict__ bk,
    const float* __restrict__ Wv, const float* __restrict__ bv)
{
    __shared__ float sWp[704];
    __shared__ float sW[4096];
    const int b = blockIdx.x, tid = threadIdx.x;
    if (b == 0) {
        for (int i = tid; i < 704; i += 256) g_fw[i] = 8.0f * Wp[i];
        if (tid < 64) g_fb[tid] = 8.0f * bp[tid];
        return;
    }
    const float* W  = (b == 1) ? Wq : (b == 2) ? Wk : Wv;
    const float* bb = (b == 1) ? bq : (b == 2) ? bk : bv;
    const float fw = (b == 1) ? 1.0f   : 8.0f;   /* 8 * (1/8 attn scale) for q */
    const float fb = (b == 1) ? 0.125f : 1.0f;
    for (int i = tid; i < 704;  i += 256) sWp[i] = Wp[i];
    for (int i = tid; i < 4096; i += 256) sW[i]  = W[i];
    __syncthreads();
    const int j = tid & 63, g = tid >> 6;
    for (int i = g; i < 11; i += 4) {
        float s = 0.0f;
        #pragma unroll 4
        for (int d = 0; d < 64; ++d) s += sWp[i*64 + d] * sW[d*64 + j];
        g_fw[b*704 + i*64 + j] = fw * s;
    }
    if (tid < 64) {
        float s = 0.0f;
        for (int d = 0; d < 64; ++d) s += bp[d] * sW[d*64 + tid];
        g_fb[b*64 + tid] = fw * s + fb * bb[tid];
    }
}

/* ------------------------------------------------------------------ */
/* K1: x,q,k,v = in @ fused.  512 thr, 64 rows/block, weights in regs */
/* ------------------------------------------------------------------ */
__global__ void __launch_bounds__(512) k_qkv(
    const float* __restrict__ inp,
    float* __restrict__ outK, float* __restrict__ outV)
{
    extern __shared__ float sm[];
    float* sW  = sm;          /* 2816 */
    float* sB  = sW + 2816;   /* 256  */
    float* sIn = sB + 256;    /* 704  */
    const int tid = threadIdx.x;
    const int row0 = blockIdx.x * 64;

    for (int i = tid; i < 2816; i += 512) sW[i] = g_fw[i];
    if (tid < 256) sB[tid] = g_fb[tid];
    for (int i = tid; i < 704; i += 512) sIn[i] = inp[(size_t)row0*11 + i];
    __syncthreads();

    const int j = tid & 63, rb = (tid >> 6) * 8;
    float wx[11], wq[11], wk[11], wv[11];
    #pragma unroll
    for (int i = 0; i < 11; ++i) {
        wx[i] = sW[i*64 + j];
        wq[i] = sW[704  + i*64 + j];
        wk[i] = sW[1408 + i*64 + j];
        wv[i] = sW[2112 + i*64 + j];
    }
    float ax[8], aq[8], ak[8], av[8];
    #pragma unroll
    for (int r = 0; r < 8; ++r) {
        ax[r] = sB[j]; aq[r] = sB[64+j]; ak[r] = sB[128+j]; av[r] = sB[192+j];
    }
    #pragma unroll
    for (int i = 0; i < 11; ++i) {
        #pragma unroll
        for (int r = 0; r < 8; ++r) {
            float in = sIn[(rb+r)*11 + i];
            ax[r] += in * wx[i];
            aq[r] += in * wq[i];
            ak[r] += in * wk[i];
            av[r] += in * wv[i];
        }
    }
    #pragma unroll
    for (int r = 0; r < 8; ++r) {
        size_t n = (size_t)(row0 + rb + r) * 64 + j;
        g_x[n]  = ax[r];
        g_q[n]  = aq[r];
        outK[n] = ak[r];
        outV[n] = av[r];
    }
}

/* ------------------------------------------------------------------ */
/* K2: causal attention, causal loop bounds, balanced warp mapping.   */
/* ------------------------------------------------------------------ */
template<int NC>
__device__ __forceinline__ void score_nc(
    const float* __restrict__ sKt, const float* __restrict__ sQ,
    int mbase, int lane, float (&sc)[5][5])
{
    #pragma unroll 2
    for (int i = 0; i < 64; ++i) {
        float kv[NC];
        #pragma unroll
        for (int c = 0; c < NC; ++c) kv[c] = sKt[i*161 + c*32 + lane];
        #pragma unroll
        for (int k = 0; k < 5; ++k) {
            float qi = sQ[(mbase+k)*64 + i];
            #pragma unroll
            for (int c = 0; c < NC; ++c) sc[k][c] += qi * kv[c];
        }
    }
}

__global__ void __launch_bounds__(256) k_attn(
    const float* __restrict__ Kin, const float* __restrict__ Vin,
    float* __restrict__ attnOut)
{
    extern __shared__ float sm[];
    float* sKt = sm;             /* 64 x 161 = 10304; reused as sA (40x160) */
    float* sV  = sKt + 10304;    /* 160 x 64 = 10240 */
    float* sQ  = sV  + 10240;    /* 40 x 64  = 2560  */
    float* sA  = sKt;

    const int tid  = threadIdx.x;
    const int lane = tid & 31;
    const int w    = tid >> 5;
    const int part = blockIdx.x >> 2;
    const int quad = blockIdx.x & 3;
    const int r    = (w < 4) ? w : 11 - w;
    const int mbase = 5 * r;
    const int tmax  = quad + 20*r + 16;
    const int nc    = (tmax >> 5) + 1;

    const float4* Kg4 = (const float4*)(Kin + (size_t)part*160*64);
    const float4* Vg4 = (const float4*)(Vin + (size_t)part*160*64);
    float4* sV4 = (float4*)sV;

    for (int idx = tid; idx < 160*16; idx += 256) {
        int s = idx >> 4, i4 = (idx & 15) * 4;
        float4 kk = Kg4[idx];
        sKt[(i4+0)*161 + s] = kk.x;
        sKt[(i4+1)*161 + s] = kk.y;
        sKt[(i4+2)*161 + s] = kk.z;
        sKt[(i4+3)*161 + s] = kk.w;
        sV4[idx] = Vg4[idx];
    }
    for (int idx = tid; idx < 40*16; idx += 256) {
        int m = idx >> 4, i4 = idx & 15;
        int row = part*160 + quad + 4*m;
        ((float4*)(sQ + m*64))[i4] = ((const float4*)(g_q + (size_t)row*64))[i4];
    }
    __syncthreads();

    float sc[5][5];
    #pragma unroll
    for (int k = 0; k < 5; ++k)
        #pragma unroll
        for (int c = 0; c < 5; ++c) sc[k][c] = 0.0f;

    switch (nc) {
        case 1: score_nc<1>(sKt, sQ, mbase, lane, sc); break;
        case 2: score_nc<2>(sKt, sQ, mbase, lane, sc); break;
        case 3: score_nc<3>(sKt, sQ, mbase, lane, sc); break;
        case 4: score_nc<4>(sKt, sQ, mbase, lane, sc); break;
        default: score_nc<5>(sKt, sQ, mbase, lane, sc); break;
    }

    #pragma unroll
    for (int k = 0; k < 5; ++k) {
        const int t = quad + 4*(mbase + k);
        float mval = -3.4e38f;
        #pragma unroll
        for (int c = 0; c < 5; ++c) {
            int s = c*32 + lane;
            if (c < nc && s <= t) mval = fmaxf(mval, sc[k][c]);
        }
        #pragma unroll
        for (int o = 16; o; o >>= 1) mval = fmaxf(mval, __shfl_xor_sync(0xffffffffu, mval, o));
        float sum = 0.0f;
        #pragma unroll
        for (int c = 0; c < 5; ++c) {
            int s = c*32 + lane;
            float p = (c < nc && s <= t) ? expf(sc[k][c] - mval) : 0.0f;
            sc[k][c] = p;
            sum += p;
        }
        #pragma unroll
        for (int o = 16; o; o >>= 1) sum += __shfl_xor_sync(0xffffffffu, sum, o);
        float inv = 1.0f / sum;
        float* arow = attnOut + (size_t)(part*160 + t)*160;
        #pragma unroll
        for (int c = 0; c < 5; ++c) {
            if (c < nc) {
                sc[k][c] *= inv;
                arow[c*32 + lane] = sc[k][c];
            } else {
                arow[c*32 + lane] = 0.0f;
            }
        }
    }

    __syncthreads();

    #pragma unroll
    for (int k = 0; k < 5; ++k) {
        #pragma unroll
        for (int c = 0; c < 5; ++c)
            if (c < nc) sA[(mbase+k)*160 + c*32 + lane] = sc[k][c];
    }
    __syncwarp();

    const float2* sV2 = (const float2*)sV;
    float2 acc[5];
    #pragma unroll
    for (int k = 0; k < 5; ++k) acc[k] = make_float2(0.f, 0.f);

    const int send = (tmax + 4) & ~3;
    for (int s = 0; s < send; s += 4) {
        float4 a[5];
        #pragma unroll
        for (int k = 0; k < 5; ++k)
            a[k] = *(const float4*)(sA + (mbase+k)*160 + s);
        float2 v0 = sV2[(s+0)*32 + lane];
        float2 v1 = sV2[(s+1)*32 + lane];
        float2 v2 = sV2[(s+2)*32 + lane];
        float2 v3 = sV2[(s+3)*32 + lane];
        #pragma unroll
        for (int k = 0; k < 5; ++k) {
            acc[k].x += a[k].x*v0.x + a[k].y*v1.x + a[k].z*v2.x + a[k].w*v3.x;
            acc[k].y += a[k].x*v0.y + a[k].y*v1.y + a[k].z*v2.y + a[k].w*v3.y;
        }
    }
    #pragma unroll
    for (int k = 0; k < 5; ++k) {
        const int t = quad + 4*(mbase + k);
        size_t n = (size_t)part*160 + t;
        ((float2*)(g_z + n*64))[lane] = acc[k];
    }
}

/* ------------------------------------------------------------------ */
/* K3: persistent epilogue, lane=row / warp=column-slice dataflow.    */
/* All GEMMs f32x2 with warp-uniform weight broadcasts; 16 warps on   */
/* every stage. Padded smem rows (68/260) keep float4 LDS phase-clean.*/
/* ------------------------------------------------------------------ */
__global__ void __launch_bounds__(512) k_epi(
    const float* __restrict__ Wo, const float* __restrict__ bo,
    const float* __restrict__ ln1g, const float* __restrict__ ln1b,
    const float* __restrict__ W1, const float* __restrict__ b1,
    const float* __restrict__ W2, const float* __restrict__ b2,
    const float* __restrict__ ln2g, const float* __restrict__ ln2b,
    const float* __restrict__ Wf, const float* __restrict__ bf,
    float* __restrict__ outR, float* __restrict__ outP, float* __restrict__ outP2)
{
    extern __shared__ float sm[];
    float* sWo = sm;            /* 4096  */
    float* sW1 = sWo + 4096;    /* 16384 */
    float* sW2 = sW1 + 16384;   /* 16384 */
    float* sC  = sW2 + 16384;   /* 704: bo|b1|b2|l1g|l1b|l2g|l2b|Wf */
    float* sZ  = sC  + 704;     /* 32 x 68 = 2176 */
    float* sO1 = sZ  + 2176;    /* 32 x 68 = 2176 */
    float* sH  = sO1 + 2176;    /* 32 x 260 = 8320 */
    float* sP  = sH  + 8320;    /* 2 x (32x68) = 4352 (also S1 out) */

    const int tid = threadIdx.x, w = tid >> 5, lane = tid & 31;

    for (int i = tid; i < 1024; i += 512) ((float4*)sWo)[i] = ((const float4*)Wo)[i];
    for (int i = tid; i < 4096; i += 512) {
        ((float4*)sW1)[i] = ((const float4*)W1)[i];
        ((float4*)sW2)[i] = ((const float4*)W2)[i];
    }
    if (tid < 64) {
        sC[tid]     = bo[tid];
        sC[320+tid] = b2[tid];
        sC[384+tid] = ln1g[tid];
        sC[448+tid] = ln1b[tid];
        sC[512+tid] = ln2g[tid];
        sC[576+tid] = ln2b[tid];
        sC[640+tid] = Wf[tid];
    }
    if (tid < 256) sC[64 + tid] = b1[tid];
    const float bfv = bf[0];
    __syncthreads();

    /* FFN1 bias pairs (warp-constant) held in regs across tiles */
    u64t bia[8];
    #pragma unroll
    for (int p = 0; p < 8; ++p) bia[p] = ((const u64t*)(sC + 64))[w*8 + p];

    const int rw = tid >> 4;        /* 0..31 row for staging/LN stages */
    const int c4 = tid & 15;

    for (int tile = blockIdx.x; tile < NROW/32; tile += gridDim.x) {
        const int row0 = tile * 32;

        /* ---- S0: stage z (coalesced) into padded sZ ---- */
        *(float4*)(sZ + rw*68 + c4*4) =
            ((const float4*)(g_z + (size_t)(row0 + rw)*64))[c4];
        __syncthreads();

        /* ---- S1: Wo gemm. warp w -> cols 4w..4w+4, lane = row ---- */
        {
            u64t acc0 = 0ull, acc1 = 0ull;
            const float* zrow  = sZ + lane*68;
            const float* wbase = sWo + 4*w;
            #pragma unroll 4
            for (int i4 = 0; i4 < 16; ++i4) {
                float4 a = *(const float4*)(zrow + i4*4);
                ulonglong2 w0 = *(const ulonglong2*)(wbase + (i4*4+0)*64);
                ulonglong2 w1 = *(const ulonglong2*)(wbase + (i4*4+1)*64);
                ulonglong2 w2 = *(const ulonglong2*)(wbase + (i4*4+2)*64);
                ulonglong2 w3 = *(const ulonglong2*)(wbase + (i4*4+3)*64);
                u64t d0 = dup2(a.x), d1 = dup2(a.y), d2 = dup2(a.z), d3 = dup2(a.w);
                fma2p(acc0, d0, w0.x); fma2p(acc1, d0, w0.y);
                fma2p(acc0, d1, w1.x); fma2p(acc1, d1, w1.y);
                fma2p(acc0, d2, w2.x); fma2p(acc1, d2, w2.y);
                fma2p(acc0, d3, w3.x); fma2p(acc1, d3, w3.y);
            }
            float4 o;
            unpack2(o.x, o.y, acc0);
            unpack2(o.z, o.w, acc1);
            *(float4*)(sP + lane*68 + 4*w) = o;
        }
        __syncthreads();

        /* ---- S2: bias + residual + LN1 -> sO1 (padded) ---- */
        {
            float4 v  = *(const float4*)(sP + rw*68 + c4*4);
            float4 b  = ((const float4*)sC)[c4];
            float4 rx = ((const float4*)(g_x + (size_t)(row0 + rw)*64))[c4];
            v.x += b.x + rx.x; v.y += b.y + rx.y;
            v.z += b.z + rx.z; v.w += b.w + rx.w;
            float s = v.x + v.y + v.z + v.w;
            #pragma unroll
            for (int o = 8; o; o >>= 1) s += __shfl_xor_sync(0xffffffffu, s, o);
            float mu = s * (1.0f/64.0f);
            float4 d = {v.x-mu, v.y-mu, v.z-mu, v.w-mu};
            float q = d.x*d.x + d.y*d.y + d.z*d.z + d.w*d.w;
            #pragma unroll
            for (int o = 8; o; o >>= 1) q += __shfl_xor_sync(0xffffffffu, q, o);
            float is = rsqrtf(q * (1.0f/64.0f) + 1e-6f);
            float4 g  = ((const float4*)(sC + 384))[c4];
            float4 bb = ((const float4*)(sC + 448))[c4];
            float4 o1 = {g.x*d.x*is + bb.x, g.y*d.y*is + bb.y,
                         g.z*d.z*is + bb.z, g.w*d.w*is + bb.w};
            *(float4*)(sO1 + rw*68 + c4*4) = o1;
        }
        __syncthreads();

        /* ---- S3: FFN1. warp w -> cols 16w..16w+16, lane = row ---- */
        {
            u64t acc[8];
            #pragma unroll
            for (int p = 0; p < 8; ++p) acc[p] = bia[p];
            const float* orow  = sO1 + lane*68;
            const float* wbase = sW1 + 16*w;
            #pragma unroll 2
            for (int i4 = 0; i4 < 16; ++i4) {
                float4 a = *(const float4*)(orow + i4*4);
                float aj[4] = {a.x, a.y, a.z, a.w};
                #pragma unroll
                for (int j = 0; j < 4; ++j) {
                    const ulonglong2* wp =
                        (const ulonglong2*)(wbase + (i4*4 + j)*256);
                    ulonglong2 wA = wp[0], wB = wp[1], wC = wp[2], wD = wp[3];
                    u64t d = dup2(aj[j]);
                    fma2p(acc[0], d, wA.x); fma2p(acc[1], d, wA.y);
                    fma2p(acc[2], d, wB.x); fma2p(acc[3], d, wB.y);
                    fma2p(acc[4], d, wC.x); fma2p(acc[5], d, wC.y);
                    fma2p(acc[6], d, wD.x); fma2p(acc[7], d, wD.y);
                }
            }
            float v[16];
            #pragma unroll
            for (int p = 0; p < 8; ++p) {
                unpack2(v[2*p], v[2*p+1], acc[p]);
                v[2*p]   = fmaxf(v[2*p],   0.0f);
                v[2*p+1] = fmaxf(v[2*p+1], 0.0f);
            }
            float* dst = sH + lane*260 + 16*w;
            ((float4*)dst)[0] = make_float4(v[0],  v[1],  v[2],  v[3]);
            ((float4*)dst)[1] = make_float4(v[4],  v[5],  v[6],  v[7]);
            ((float4*)dst)[2] = make_float4(v[8],  v[9],  v[10], v[11]);
            ((float4*)dst)[3] = make_float4(v[12], v[13], v[14], v[15]);
        }
        __syncthreads();

        /* ---- S4: FFN2. warp (wc,wk): cols 8wc..8wc+8, K-half wk ---- */
        {
            const int wc = w & 7, wk = w >> 3;
            u64t acc[4] = {0ull, 0ull, 0ull, 0ull};
            const float* hrow  = sH + lane*260 + wk*128;
            const float* wbase = sW2 + 8*wc + wk*128*64;
            #pragma unroll 2
            for (int i4 = 0; i4 < 32; ++i4) {
                float4 a = *(const float4*)(hrow + i4*4);
                float aj[4] = {a.x, a.y, a.z, a.w};
                #pragma unroll
                for (int j = 0; j < 4; ++j) {
                    const ulonglong2* wp =
                        (const ulonglong2*)(wbase + (i4*4 + j)*64);
                    ulonglong2 wA = wp[0], wB = wp[1];
                    u64t d = dup2(aj[j]);
                    fma2p(acc[0], d, wA.x); fma2p(acc[1], d, wA.y);
                    fma2p(acc[2], d, wB.x); fma2p(acc[3], d, wB.y);
                }
            }
            float v[8];
            #pragma unroll
            for (int p = 0; p < 4; ++p) unpack2(v[2*p], v[2*p+1], acc[p]);
            float* dst = sP + wk*2176 + lane*68 + 8*wc;
            ((float4*)dst)[0] = make_float4(v[0], v[1], v[2], v[3]);
            ((float4*)dst)[1] = make_float4(v[4], v[5], v[6], v[7]);
        }
        __syncthreads();

        /* ---- S5: reduce halves + bias + residual + LN2 + outputs ---- */
        {
            float4 v  = *(const float4*)(sP + rw*68 + c4*4);
            float4 v1 = *(const float4*)(sP + 2176 + rw*68 + c4*4);
            float4 b  = ((const float4*)(sC + 320))[c4];
            float4 rs = *(const float4*)(sO1 + rw*68 + c4*4);
            v.x += v1.x + b.x + rs.x;
            v.y += v1.y + b.y + rs.y;
            v.z += v1.z + b.z + rs.z;
            v.w += v1.w + b.w + rs.w;
            float s = v.x + v.y + v.z + v.w;
            #pragma unroll
            for (int o = 8; o; o >>= 1) s += __shfl_xor_sync(0xffffffffu, s, o);
            float mu = s * (1.0f/64.0f);
            float4 d = {v.x-mu, v.y-mu, v.z-mu, v.w-mu};
            float q = d.x*d.x + d.y*d.y + d.z*d.z + d.w*d.w;
            #pragma unroll
            for (int o = 8; o; o >>= 1) q += __shfl_xor_sync(0xffffffffu, q, o);
            float is = rsqrtf(q * (1.0f/64.0f) + 1e-6f);
            float4 g  = ((const float4*)(sC + 512))[c4];
            float4 bb = ((const float4*)(sC + 576))[c4];
            float4 rv = {g.x*d.x*is + bb.x, g.y*d.y*is + bb.y,
                         g.z*d.z*is + bb.z, g.w*d.w*is + bb.w};
            const size_t n = (size_t)row0 + rw;
            ((float4*)(outR + n*64))[c4] = rv;
            float4 wf = ((const float4*)(sC + 640))[c4];
            float pp = rv.x*wf.x + rv.y*wf.y + rv.z*wf.z + rv.w*wf.w;
            #pragma unroll
            for (int o = 8; o; o >>= 1) pp += __shfl_xor_sync(0xffffffffu, pp, o);
            if (c4 == 0) {
                float pv = pp + bfv;
                outP[n]  = pv;
                outP2[n] = pv;
            }
        }
        __syncthreads();
    }
}

/* ------------------------------------------------------------------ */
extern "C" void kernel_launch(void* const* d_in, const int* in_sizes, int n_in,
                              void* d_out, int out_size)
{
    (void)in_sizes; (void)n_in; (void)out_size;
    const float* inputs = (const float*)d_in[0];
    const float* Wp  = (const float*)d_in[2];
    const float* bp  = (const float*)d_in[3];
    const float* Wq  = (const float*)d_in[4];
    const float* bq  = (const float*)d_in[5];
    const float* Wk  = (const float*)d_in[6];
    const float* bk  = (const float*)d_in[7];
    const float* Wv  = (const float*)d_in[8];
    const float* bv  = (const float*)d_in[9];
    const float* Wo  = (const float*)d_in[10];
    const float* bo  = (const float*)d_in[11];
    const float* l1g = (const float*)d_in[12];
    const float* l1b = (const float*)d_in[13];
    const float* W1  = (const float*)d_in[14];
    const float* b1  = (const float*)d_in[15];
    const float* W2  = (const float*)d_in[16];
    const float* b2  = (const float*)d_in[17];
    const float* l2g = (const float*)d_in[18];
    const float* l2b = (const float*)d_in[19];
    const float* Wf  = (const float*)d_in[20];
    const float* bf  = (const float*)d_in[21];
    float* out = (float*)d_out;

    const size_t sm1 = (size_t)(2816 + 256 + 704) * 4;                          /* ~15 KB  */
    const size_t sm2 = (size_t)(10304 + 10240 + 2560) * 4;                      /* ~92 KB  */
    const size_t sm3 = (size_t)(4096 + 16384 + 16384 + 704 + 2176 + 2176 + 8320 + 4352) * 4; /* ~213 KB */

    cudaFuncSetAttribute(k_qkv,  cudaFuncAttributeMaxDynamicSharedMemorySize, (int)sm1);
    cudaFuncSetAttribute(k_attn, cudaFuncAttributeMaxDynamicSharedMemorySize, (int)sm2);
    cudaFuncSetAttribute(k_epi,  cudaFuncAttributeMaxDynamicSharedMemorySize, (int)sm3);

    k_fold<<<4, 256>>>(Wp, bp, Wq, bq, Wk, bk, Wv, bv);
    k_qkv<<<NROW/64, 512, sm1>>>(inputs, out + OFF_K, out + OFF_V);
    k_attn<<<NPART*4, 256, sm2>>>(out + OFF_K, out + OFF_V, out + OFF_ATTN);
    k_epi<<<148, 512, sm3>>>(Wo, bo, l1g, l1b, W1, b1, W2, b2, l2g, l2b, Wf, bf,
                             out + OFF_R, out + OFF_PRED, out + OFF_PRED2);
}

// round 9
// speedup vs baseline: 1.0270x; 1.0270x over previous
#include <cuda_runtime.h>

#define B_ 8
#define P_ 10
#define S_ 160
#define FX_ 11
#define D_ 64
#define DFF_ 256
#define NROW (B_*P_*S_)   /* 12800 */
#define NPART (B_*P_)     /* 80 */

/* output layout (tuple order): pred, pred_resampl, K, V, R, attn_weights */
#define OFF_PRED  0
#define OFF_PRED2 (NROW)
#define OFF_K     (2*NROW)
#define OFF_V     (OFF_K + NROW*D_)
#define OFF_R     (OFF_V + NROW*D_)
#define OFF_ATTN  (OFF_R + NROW*D_)

/* scratch (no cudaMalloc allowed) */
__device__ float g_x[NROW*D_];
__device__ float g_q[NROW*D_];
__device__ float g_z[NROW*D_];
__device__ float g_fw[4*704];   /* fused 11x64 weights: x,q,k,v */
__device__ float g_fb[4*64];    /* fused biases */

typedef unsigned long long u64t;

__device__ __forceinline__ void fma2p(u64t& acc, u64t a, u64t b) {
    asm("fma.rn.f32x2 %0, %1, %2, %0;" : "+l"(acc) : "l"(a), "l"(b));
}
__device__ __forceinline__ void unpack2(float& lo, float& hi, u64t v) {
    asm("mov.b64 {%0, %1}, %2;" : "=f"(lo), "=f"(hi) : "l"(v));
}

/* ------------------------------------------------------------------ */
/* K0: fold Wp into Wq/Wk/Wv. Attention scale 1/8 folded into Wq.     */
/* ------------------------------------------------------------------ */
__global__ void __launch_bounds__(256) k_fold(
    const float* __restrict__ Wp, const float* __restrict__ bp,
    const float* __restrict__ Wq, const float* __restrict__ bq,
    const float* __restrict__ Wk, const float* __restrict__ bk,
    const float* __restrict__ Wv, const float* __restrict__ bv)
{
    __shared__ float sWp[704];
    __shared__ float sW[4096];
    const int b = blockIdx.x, tid = threadIdx.x;
    if (b == 0) {
        for (int i = tid; i < 704; i += 256) g_fw[i] = 8.0f * Wp[i];
        if (tid < 64) g_fb[tid] = 8.0f * bp[tid];
        return;
    }
    const float* W  = (b == 1) ? Wq : (b == 2) ? Wk : Wv;
    const float* bb = (b == 1) ? bq : (b == 2) ? bk : bv;
    const float fw = (b == 1) ? 1.0f   : 8.0f;   /* 8 * (1/8 attn scale) for q */
    const float fb = (b == 1) ? 0.125f : 1.0f;
    for (int i = tid; i < 704;  i += 256) sWp[i] = Wp[i];
    for (int i = tid; i < 4096; i += 256) sW[i]  = W[i];
    __syncthreads();
    const int j = tid & 63, g = tid >> 6;
    for (int i = g; i < 11; i += 4) {
        float s = 0.0f;
        #pragma unroll 4
        for (int d = 0; d < 64; ++d) s += sWp[i*64 + d] * sW[d*64 + j];
        g_fw[b*704 + i*64 + j] = fw * s;
    }
    if (tid < 64) {
        float s = 0.0f;
        for (int d = 0; d < 64; ++d) s += bp[d] * sW[d*64 + tid];
        g_fb[b*64 + tid] = fw * s + fb * bb[tid];
    }
}

/* ------------------------------------------------------------------ */
/* K1: x,q,k,v = in @ fused.  512 thr, 64 rows/block, weights in regs */
/* ------------------------------------------------------------------ */
__global__ void __launch_bounds__(512) k_qkv(
    const float* __restrict__ inp,
    float* __restrict__ outK, float* __restrict__ outV)
{
    extern __shared__ float sm[];
    float* sW  = sm;          /* 2816 */
    float* sB  = sW + 2816;   /* 256  */
    float* sIn = sB + 256;    /* 704  */
    const int tid = threadIdx.x;
    const int row0 = blockIdx.x * 64;

    for (int i = tid; i < 2816; i += 512) sW[i] = g_fw[i];
    if (tid < 256) sB[tid] = g_fb[tid];
    for (int i = tid; i < 704; i += 512) sIn[i] = inp[(size_t)row0*11 + i];
    __syncthreads();

    const int j = tid & 63, rb = (tid >> 6) * 8;
    float wx[11], wq[11], wk[11], wv[11];
    #pragma unroll
    for (int i = 0; i < 11; ++i) {
        wx[i] = sW[i*64 + j];
        wq[i] = sW[704  + i*64 + j];
        wk[i] = sW[1408 + i*64 + j];
        wv[i] = sW[2112 + i*64 + j];
    }
    float ax[8], aq[8], ak[8], av[8];
    #pragma unroll
    for (int r = 0; r < 8; ++r) {
        ax[r] = sB[j]; aq[r] = sB[64+j]; ak[r] = sB[128+j]; av[r] = sB[192+j];
    }
    #pragma unroll
    for (int i = 0; i < 11; ++i) {
        #pragma unroll
        for (int r = 0; r < 8; ++r) {
            float in = sIn[(rb+r)*11 + i];
            ax[r] += in * wx[i];
            aq[r] += in * wq[i];
            ak[r] += in * wk[i];
            av[r] += in * wv[i];
        }
    }
    #pragma unroll
    for (int r = 0; r < 8; ++r) {
        size_t n = (size_t)(row0 + rb + r) * 64 + j;
        g_x[n]  = ax[r];
        g_q[n]  = aq[r];
        outK[n] = ak[r];
        outV[n] = av[r];
    }
}

/* ------------------------------------------------------------------ */
/* K2: causal attention, causal loop bounds, balanced warp mapping.   */
/* ------------------------------------------------------------------ */
template<int NC>
__device__ __forceinline__ void score_nc(
    const float* __restrict__ sKt, const float* __restrict__ sQ,
    int mbase, int lane, float (&sc)[5][5])
{
    #pragma unroll 2
    for (int i = 0; i < 64; ++i) {
        float kv[NC];
        #pragma unroll
        for (int c = 0; c < NC; ++c) kv[c] = sKt[i*161 + c*32 + lane];
        #pragma unroll
        for (int k = 0; k < 5; ++k) {
            float qi = sQ[(mbase+k)*64 + i];
            #pragma unroll
            for (int c = 0; c < NC; ++c) sc[k][c] += qi * kv[c];
        }
    }
}

__global__ void __launch_bounds__(256) k_attn(
    const float* __restrict__ Kin, const float* __restrict__ Vin,
    float* __restrict__ attnOut)
{
    extern __shared__ float sm[];
    float* sKt = sm;             /* 64 x 161 = 10304; reused as sA (40x160) */
    float* sV  = sKt + 10304;    /* 160 x 64 = 10240 */
    float* sQ  = sV  + 10240;    /* 40 x 64  = 2560  */
    float* sA  = sKt;

    const int tid  = threadIdx.x;
    const int lane = tid & 31;
    const int w    = tid >> 5;
    const int part = blockIdx.x >> 2;
    const int quad = blockIdx.x & 3;
    const int r    = (w < 4) ? w : 11 - w;
    const int mbase = 5 * r;
    const int tmax  = quad + 20*r + 16;
    const int nc    = (tmax >> 5) + 1;

    const float4* Kg4 = (const float4*)(Kin + (size_t)part*160*64);
    const float4* Vg4 = (const float4*)(Vin + (size_t)part*160*64);
    float4* sV4 = (float4*)sV;

    for (int idx = tid; idx < 160*16; idx += 256) {
        int s = idx >> 4, i4 = (idx & 15) * 4;
        float4 kk = Kg4[idx];
        sKt[(i4+0)*161 + s] = kk.x;
        sKt[(i4+1)*161 + s] = kk.y;
        sKt[(i4+2)*161 + s] = kk.z;
        sKt[(i4+3)*161 + s] = kk.w;
        sV4[idx] = Vg4[idx];
    }
    for (int idx = tid; idx < 40*16; idx += 256) {
        int m = idx >> 4, i4 = idx & 15;
        int row = part*160 + quad + 4*m;
        ((float4*)(sQ + m*64))[i4] = ((const float4*)(g_q + (size_t)row*64))[i4];
    }
    __syncthreads();

    float sc[5][5];
    #pragma unroll
    for (int k = 0; k < 5; ++k)
        #pragma unroll
        for (int c = 0; c < 5; ++c) sc[k][c] = 0.0f;

    switch (nc) {
        case 1: score_nc<1>(sKt, sQ, mbase, lane, sc); break;
        case 2: score_nc<2>(sKt, sQ, mbase, lane, sc); break;
        case 3: score_nc<3>(sKt, sQ, mbase, lane, sc); break;
        case 4: score_nc<4>(sKt, sQ, mbase, lane, sc); break;
        default: score_nc<5>(sKt, sQ, mbase, lane, sc); break;
    }

    #pragma unroll
    for (int k = 0; k < 5; ++k) {
        const int t = quad + 4*(mbase + k);
        float mval = -3.4e38f;
        #pragma unroll
        for (int c = 0; c < 5; ++c) {
            int s = c*32 + lane;
            if (c < nc && s <= t) mval = fmaxf(mval, sc[k][c]);
        }
        #pragma unroll
        for (int o = 16; o; o >>= 1) mval = fmaxf(mval, __shfl_xor_sync(0xffffffffu, mval, o));
        float sum = 0.0f;
        #pragma unroll
        for (int c = 0; c < 5; ++c) {
            int s = c*32 + lane;
            float p = (c < nc && s <= t) ? expf(sc[k][c] - mval) : 0.0f;
            sc[k][c] = p;
            sum += p;
        }
        #pragma unroll
        for (int o = 16; o; o >>= 1) sum += __shfl_xor_sync(0xffffffffu, sum, o);
        float inv = 1.0f / sum;
        float* arow = attnOut + (size_t)(part*160 + t)*160;
        #pragma unroll
        for (int c = 0; c < 5; ++c) {
            if (c < nc) {
                sc[k][c] *= inv;
                arow[c*32 + lane] = sc[k][c];
            } else {
                arow[c*32 + lane] = 0.0f;
            }
        }
    }

    __syncthreads();

    #pragma unroll
    for (int k = 0; k < 5; ++k) {
        #pragma unroll
        for (int c = 0; c < 5; ++c)
            if (c < nc) sA[(mbase+k)*160 + c*32 + lane] = sc[k][c];
    }
    __syncwarp();

    const float2* sV2 = (const float2*)sV;
    float2 acc[5];
    #pragma unroll
    for (int k = 0; k < 5; ++k) acc[k] = make_float2(0.f, 0.f);

    const int send = (tmax + 4) & ~3;
    for (int s = 0; s < send; s += 4) {
        float4 a[5];
        #pragma unroll
        for (int k = 0; k < 5; ++k)
            a[k] = *(const float4*)(sA + (mbase+k)*160 + s);
        float2 v0 = sV2[(s+0)*32 + lane];
        float2 v1 = sV2[(s+1)*32 + lane];
        float2 v2 = sV2[(s+2)*32 + lane];
        float2 v3 = sV2[(s+3)*32 + lane];
        #pragma unroll
        for (int k = 0; k < 5; ++k) {
            acc[k].x += a[k].x*v0.x + a[k].y*v1.x + a[k].z*v2.x + a[k].w*v3.x;
            acc[k].y += a[k].x*v0.y + a[k].y*v1.y + a[k].z*v2.y + a[k].w*v3.y;
        }
    }
    #pragma unroll
    for (int k = 0; k < 5; ++k) {
        const int t = quad + 4*(mbase + k);
        size_t n = (size_t)part*160 + t;
        ((float2*)(g_z + n*64))[lane] = acc[k];
    }
}

/* ------------------------------------------------------------------ */
/* K3: persistent epilogue, 32-row tiles. K-packed f32x2 GEMMs using  */
/* transposed weight copies in smem: both FMA2 operands are natural   */
/* 64-bit loads, no dup instructions. 4x4 thread tiles, K-splits.     */
/* ------------------------------------------------------------------ */
__global__ void __launch_bounds__(512) k_epi(
    const float* __restrict__ Wo, const float* __restrict__ bo,
    const float* __restrict__ ln1g, const float* __restrict__ ln1b,
    const float* __restrict__ W1, const float* __restrict__ b1,
    const float* __restrict__ W2, const float* __restrict__ b2,
    const float* __restrict__ ln2g, const float* __restrict__ ln2b,
    const float* __restrict__ Wf, const float* __restrict__ bf,
    float* __restrict__ outR, float* __restrict__ outP, float* __restrict__ outP2)
{
    extern __shared__ float sm[];
    float* sWot = sm;             /* 64 x 68  = 4352  : Wo^T [c][k] */
    float* sW1t = sWot + 4352;    /* 256 x 68 = 17408 : W1^T [c][k] */
    float* sW2t = sW1t + 17408;   /* 64 x 260 = 16640 : W2^T [c][k] */
    float* sC   = sW2t + 16640;   /* 704: bo|b1|b2|l1g|l1b|l2g|l2b|Wf */
    float* sO1  = sC + 704;       /* 32 x 68 = 2176 */
    float* sH   = sO1 + 2176;     /* 32 x 260 = 8320 */
    float* sP   = sH + 8320;      /* 4 x 2048 = 8192 partials */

    const int tid = threadIdx.x;

    /* prologue: transpose weights into smem (one-time) */
    for (int i = tid; i < 4096; i += 512) {
        int k = i >> 6, c = i & 63;
        sWot[c*68 + k] = Wo[i];
    }
    for (int i = tid; i < 16384; i += 512) {
        int k = i >> 8, c = i & 255;
        sW1t[c*68 + k] = W1[i];
    }
    for (int i = tid; i < 16384; i += 512) {
        int k = i >> 6, c = i & 63;
        sW2t[c*260 + k] = W2[i];
    }
    if (tid < 64) {
        sC[tid]     = bo[tid];
        sC[320+tid] = b2[tid];
        sC[384+tid] = ln1g[tid];
        sC[448+tid] = ln1b[tid];
        sC[512+tid] = ln2g[tid];
        sC[576+tid] = ln2b[tid];
        sC[640+tid] = Wf[tid];
    }
    if (tid < 256) sC[64 + tid] = b1[tid];
    const float bfv = bf[0];
    __syncthreads();

    const int rw = tid >> 4;        /* 0..31 row for reduce/LN stages */
    const int c4 = tid & 15;
    const int isp = tid >> 7;       /* 0..3 K-split for Wo/FFN2 */
    const int t1  = tid & 127;
    const int cqs = t1 & 15;        /* col base (split stages): cols cqs+16j */
    const int rqs = t1 >> 4;        /* 0..7 rows 4rqs.. (split stages) */
    const int cqf = tid & 63;       /* FFN1 col base: cols cqf+64j */
    const int rqf = tid >> 6;       /* 0..7 FFN1 rows 4rqf.. */

    for (int tile = blockIdx.x; tile < NROW/32; tile += gridDim.x) {
        const int row0 = tile * 32;

        /* ---- S1: Wo. 4-way K-split (16 k), 4 rows x 4 cols, K-packed ---- */
        {
            u64t acc[4][4];
            #pragma unroll
            for (int r = 0; r < 4; ++r)
                #pragma unroll
                for (int j = 0; j < 4; ++j) acc[r][j] = 0ull;
            const int kb = isp * 16;
            #pragma unroll
            for (int k4 = 0; k4 < 4; ++k4) {
                const int kk = kb + k4*4;
                ulonglong2 w0 = *(const ulonglong2*)(sWot + (cqs+ 0)*68 + kk);
                ulonglong2 w1 = *(const ulonglong2*)(sWot + (cqs+16)*68 + kk);
                ulonglong2 w2 = *(const ulonglong2*)(sWot + (cqs+32)*68 + kk);
                ulonglong2 w3 = *(const ulonglong2*)(sWot + (cqs+48)*68 + kk);
                #pragma unroll
                for (int r = 0; r < 4; ++r) {
                    ulonglong2 av = *(const ulonglong2*)
                        (g_z + (size_t)(row0 + 4*rqs + r)*64 + kk);
                    fma2p(acc[r][0], av.x, w0.x); fma2p(acc[r][0], av.y, w0.y);
                    fma2p(acc[r][1], av.x, w1.x); fma2p(acc[r][1], av.y, w1.y);
                    fma2p(acc[r][2], av.x, w2.x); fma2p(acc[r][2], av.y, w2.y);
                    fma2p(acc[r][3], av.x, w3.x); fma2p(acc[r][3], av.y, w3.y);
                }
            }
            float* dst = sP + isp*2048;
            #pragma unroll
            for (int r = 0; r < 4; ++r)
                #pragma unroll
                for (int j = 0; j < 4; ++j) {
                    float lo, hi;
                    unpack2(lo, hi, acc[r][j]);
                    dst[(4*rqs + r)*64 + cqs + 16*j] = lo + hi;
                }
        }
        __syncthreads();

        /* ---- S2: reduce 4 + bias + residual + LN1 -> sO1 ---- */
        {
            float4 v  = *(const float4*)(sP +        rw*64 + 4*c4);
            float4 v1 = *(const float4*)(sP + 2048 + rw*64 + 4*c4);
            float4 v2 = *(const float4*)(sP + 4096 + rw*64 + 4*c4);
            float4 v3 = *(const float4*)(sP + 6144 + rw*64 + 4*c4);
            float4 b  = ((const float4*)sC)[c4];
            float4 rx = ((const float4*)(g_x + (size_t)(row0 + rw)*64))[c4];
            v.x += v1.x + v2.x + v3.x + b.x + rx.x;
            v.y += v1.y + v2.y + v3.y + b.y + rx.y;
            v.z += v1.z + v2.z + v3.z + b.z + rx.z;
            v.w += v1.w + v2.w + v3.w + b.w + rx.w;
            float s = v.x + v.y + v.z + v.w;
            #pragma unroll
            for (int o = 8; o; o >>= 1) s += __shfl_xor_sync(0xffffffffu, s, o);
            float mu = s * (1.0f/64.0f);
            float4 d = {v.x-mu, v.y-mu, v.z-mu, v.w-mu};
            float q = d.x*d.x + d.y*d.y + d.z*d.z + d.w*d.w;
            #pragma unroll
            for (int o = 8; o; o >>= 1) q += __shfl_xor_sync(0xffffffffu, q, o);
            float is = rsqrtf(q * (1.0f/64.0f) + 1e-6f);
            float4 g  = ((const float4*)(sC + 384))[c4];
            float4 bb = ((const float4*)(sC + 448))[c4];
            *(float4*)(sO1 + rw*68 + 4*c4) =
                make_float4(g.x*d.x*is + bb.x, g.y*d.y*is + bb.y,
                            g.z*d.z*is + bb.z, g.w*d.w*is + bb.w);
        }
        __syncthreads();

        /* ---- S3: FFN1 (K=64), 4 rows x 4 cols (cols cqf+64j), relu ---- */
        {
            u64t acc[4][4];
            #pragma unroll
            for (int r = 0; r < 4; ++r)
                #pragma unroll
                for (int j = 0; j < 4; ++j) acc[r][j] = 0ull;
            #pragma unroll 4
            for (int k4 = 0; k4 < 16; ++k4) {
                const int kk = k4*4;
                ulonglong2 w0 = *(const ulonglong2*)(sW1t + (cqf+  0)*68 + kk);
                ulonglong2 w1 = *(const ulonglong2*)(sW1t + (cqf+ 64)*68 + kk);
                ulonglong2 w2 = *(const ulonglong2*)(sW1t + (cqf+128)*68 + kk);
                ulonglong2 w3 = *(const ulonglong2*)(sW1t + (cqf+192)*68 + kk);
                #pragma unroll
                for (int r = 0; r < 4; ++r) {
                    ulonglong2 av = *(const ulonglong2*)
                        (sO1 + (4*rqf + r)*68 + kk);
                    fma2p(acc[r][0], av.x, w0.x); fma2p(acc[r][0], av.y, w0.y);
                    fma2p(acc[r][1], av.x, w1.x); fma2p(acc[r][1], av.y, w1.y);
                    fma2p(acc[r][2], av.x, w2.x); fma2p(acc[r][2], av.y, w2.y);
                    fma2p(acc[r][3], av.x, w3.x); fma2p(acc[r][3], av.y, w3.y);
                }
            }
            #pragma unroll
            for (int r = 0; r < 4; ++r)
                #pragma unroll
                for (int j = 0; j < 4; ++j) {
                    float lo, hi;
                    unpack2(lo, hi, acc[r][j]);
                    sH[(4*rqf + r)*260 + cqf + 64*j] =
                        fmaxf(lo + hi + sC[64 + cqf + 64*j], 0.0f);
                }
        }
        __syncthreads();

        /* ---- S4: FFN2. 4-way K-split (64 k), 4 rows x 4 cols ---- */
        {
            u64t acc[4][4];
            #pragma unroll
            for (int r = 0; r < 4; ++r)
                #pragma unroll
                for (int j = 0; j < 4; ++j) acc[r][j] = 0ull;
            const int kb = isp * 64;
            #pragma unroll 4
            for (int k4 = 0; k4 < 16; ++k4) {
                const int kk = kb + k4*4;
                ulonglong2 w0 = *(const ulonglong2*)(sW2t + (cqs+ 0)*260 + kk);
                ulonglong2 w1 = *(const ulonglong2*)(sW2t + (cqs+16)*260 + kk);
                ulonglong2 w2 = *(const ulonglong2*)(sW2t + (cqs+32)*260 + kk);
                ulonglong2 w3 = *(const ulonglong2*)(sW2t + (cqs+48)*260 + kk);
                #pragma unroll
                for (int r = 0; r < 4; ++r) {
                    ulonglong2 av = *(const ulonglong2*)
                        (sH + (4*rqs + r)*260 + kk);
                    fma2p(acc[r][0], av.x, w0.x); fma2p(acc[r][0], av.y, w0.y);
                    fma2p(acc[r][1], av.x, w1.x); fma2p(acc[r][1], av.y, w1.y);
                    fma2p(acc[r][2], av.x, w2.x); fma2p(acc[r][2], av.y, w2.y);
                    fma2p(acc[r][3], av.x, w3.x); fma2p(acc[r][3], av.y, w3.y);
                }
            }
            float* dst = sP + isp*2048;
            #pragma unroll
            for (int r = 0; r < 4; ++r)
                #pragma unroll
                for (int j = 0; j < 4; ++j) {
                    float lo, hi;
                    unpack2(lo, hi, acc[r][j]);
                    dst[(4*rqs + r)*64 + cqs + 16*j] = lo + hi;
                }
        }
        __syncthreads();

        /* ---- S5: reduce 4 + bias + residual + LN2 + outputs ---- */
        {
            float4 v  = *(const float4*)(sP +        rw*64 + 4*c4);
            float4 v1 = *(const float4*)(sP + 2048 + rw*64 + 4*c4);
            float4 v2 = *(const float4*)(sP + 4096 + rw*64 + 4*c4);
            float4 v3 = *(const float4*)(sP + 6144 + rw*64 + 4*c4);
            float4 b  = ((const float4*)(sC + 320))[c4];
            float4 rs = *(const float4*)(sO1 + rw*68 + 4*c4);
            v.x += v1.x + v2.x + v3.x + b.x + rs.x;
            v.y += v1.y + v2.y + v3.y + b.y + rs.y;
            v.z += v1.z + v2.z + v3.z + b.z + rs.z;
            v.w += v1.w + v2.w + v3.w + b.w + rs.w;
            float s = v.x + v.y + v.z + v.w;
            #pragma unroll
            for (int o = 8; o; o >>= 1) s += __shfl_xor_sync(0xffffffffu, s, o);
            float mu = s * (1.0f/64.0f);
            float4 d = {v.x-mu, v.y-mu, v.z-mu, v.w-mu};
            float q = d.x*d.x + d.y*d.y + d.z*d.z + d.w*d.w;
            #pragma unroll
            for (int o = 8; o; o >>= 1) q += __shfl_xor_sync(0xffffffffu, q, o);
            float is = rsqrtf(q * (1.0f/64.0f) + 1e-6f);
            float4 g  = ((const float4*)(sC + 512))[c4];
            float4 bb = ((const float4*)(sC + 576))[c4];
            float4 rv = {g.x*d.x*is + bb.x, g.y*d.y*is + bb.y,
                         g.z*d.z*is + bb.z, g.w*d.w*is + bb.w};
            const size_t n = (size_t)row0 + rw;
            ((float4*)(outR + n*64))[c4] = rv;
            float4 wf = ((const float4*)(sC + 640))[c4];
            float pp = rv.x*wf.x + rv.y*wf.y + rv.z*wf.z + rv.w*wf.w;
            #pragma unroll
            for (int o = 8; o; o >>= 1) pp += __shfl_xor_sync(0xffffffffu, pp, o);
            if (c4 == 0) {
                float pv = pp + bfv;
                outP[n]  = pv;
                outP2[n] = pv;
            }
        }
        __syncthreads();
    }
}

/* ------------------------------------------------------------------ */
extern "C" void kernel_launch(void* const* d_in, const int* in_sizes, int n_in,
                              void* d_out, int out_size)
{
    (void)in_sizes; (void)n_in; (void)out_size;
    const float* inputs = (const float*)d_in[0];
    const float* Wp  = (const float*)d_in[2];
    const float* bp  = (const float*)d_in[3];
    const float* Wq  = (const float*)d_in[4];
    const float* bq  = (const float*)d_in[5];
    const float* Wk  = (const float*)d_in[6];
    const float* bk  = (const float*)d_in[7];
    const float* Wv  = (const float*)d_in[8];
    const float* bv  = (const float*)d_in[9];
    const float* Wo  = (const float*)d_in[10];
    const float* bo  = (const float*)d_in[11];
    const float* l1g = (const float*)d_in[12];
    const float* l1b = (const float*)d_in[13];
    const float* W1  = (const float*)d_in[14];
    const float* b1  = (const float*)d_in[15];
    const float* W2  = (const float*)d_in[16];
    const float* b2  = (const float*)d_in[17];
    const float* l2g = (const float*)d_in[18];
    const float* l2b = (const float*)d_in[19];
    const float* Wf  = (const float*)d_in[20];
    const float* bf  = (const float*)d_in[21];
    float* out = (float*)d_out;

    const size_t sm1 = (size_t)(2816 + 256 + 704) * 4;                          /* ~15 KB  */
    const size_t sm2 = (size_t)(10304 + 10240 + 2560) * 4;                      /* ~92 KB  */
    const size_t sm3 = (size_t)(4352 + 17408 + 16640 + 704 + 2176 + 8320 + 8192) * 4; /* 231168 B */

    cudaFuncSetAttribute(k_qkv,  cudaFuncAttributeMaxDynamicSharedMemorySize, (int)sm1);
    cudaFuncSetAttribute(k_attn, cudaFuncAttributeMaxDynamicSharedMemorySize, (int)sm2);
    cudaFuncSetAttribute(k_epi,  cudaFuncAttributeMaxDynamicSharedMemorySize, (int)sm3);

    k_fold<<<4, 256>>>(Wp, bp, Wq, bq, Wk, bk, Wv, bv);
    k_qkv<<<NROW/64, 512, sm1>>>(inputs, out + OFF_K, out + OFF_V);
    k_attn<<<NPART*4, 256, sm2>>>(out + OFF_K, out + OFF_V, out + OFF_ATTN);
    k_epi<<<148, 512, sm3>>>(Wo, bo, l1g, l1b, W1, b1, W2, b2, l2g, l2b, Wf, bf,
                             out + OFF_R, out + OFF_PRED, out + OFF_PRED2);
}